// round 13
// baseline (speedup 1.0000x reference)
#include <cuda_runtime.h>
#include <cuda_fp16.h>
#include <cstdint>

#define H 128
#define N_USER_MAX 100000
#define N_ITEM_MAX 50000

// Precomputed projections stored as fp16 (halves edge gather traffic).
__device__ __half g_p_user[(size_t)N_USER_MAX * H];
__device__ __half g_p_item[(size_t)N_ITEM_MAX * H];

// W1 pre-packed into fp16 m16n8k16 B-fragments.
// Layout [table(2)][kchunk(8)][tpair(8)][lane(32)] uint4 =
//   { b0(coltile 2tp), b1(coltile 2tp), b0(coltile 2tp+1), b1(coltile 2tp+1) }
// For coltile with col base c, lane l: n = c + l/4, k0 = 16*kc + (l%4)*2;
//   b0 = half2(W[k0][n], W[k0+1][n]);  b1 = half2(W[k0+8][n], W[k0+9][n]).
__device__ uint4 g_wfrag16[2 * 8 * 8 * 32];

#define MMA_F16(d, A0, A1, A2, A3, B0, B1)                                   \
    asm volatile(                                                            \
        "mma.sync.aligned.m16n8k16.row.col.f32.f16.f16.f32 "                 \
        "{%0,%1,%2,%3}, {%4,%5,%6,%7}, {%8,%9}, {%0,%1,%2,%3};"              \
        : "+f"(d[0]), "+f"(d[1]), "+f"(d[2]), "+f"(d[3])                     \
        : "r"(A0), "r"(A1), "r"(A2), "r"(A3), "r"(B0), "r"(B1))

__device__ __forceinline__ uint32_t smem_u32(const void* p) {
    uint32_t a;
    asm("{ .reg .u64 t; cvta.to.shared.u64 t, %1; cvt.u32.u64 %0, t; }"
        : "=r"(a) : "l"(p));
    return a;
}

// ---------------------------------------------------------------------------
// convert_w: pack W1 (2H x H fp32) into fp16 B-fragments. 4096 threads.
// ---------------------------------------------------------------------------
__global__ __launch_bounds__(256) void convert_w(const float* __restrict__ W1)
{
    int idx = blockIdx.x * 256 + threadIdx.x;   // 0..4095
    int lane = idx & 31;
    int tp   = (idx >> 5) & 7;
    int kc   = (idx >> 8) & 7;
    int tb   = idx >> 11;

    const float* Wb = W1 + tb * H * H;
    int n0 = 16 * tp + (lane >> 2);
    int n1 = n0 + 8;
    int k0 = 16 * kc + (lane & 3) * 2;

    __half2 b0a = __floats2half2_rn(Wb[(size_t)k0 * H + n0],
                                    Wb[(size_t)(k0 + 1) * H + n0]);
    __half2 b1a = __floats2half2_rn(Wb[(size_t)(k0 + 8) * H + n0],
                                    Wb[(size_t)(k0 + 9) * H + n0]);
    __half2 b0b = __floats2half2_rn(Wb[(size_t)k0 * H + n1],
                                    Wb[(size_t)(k0 + 1) * H + n1]);
    __half2 b1b = __floats2half2_rn(Wb[(size_t)(k0 + 8) * H + n1],
                                    Wb[(size_t)(k0 + 9) * H + n1]);

    uint4 o;
    o.x = *reinterpret_cast<uint32_t*>(&b0a);
    o.y = *reinterpret_cast<uint32_t*>(&b1a);
    o.z = *reinterpret_cast<uint32_t*>(&b0b);
    o.w = *reinterpret_cast<uint32_t*>(&b1b);
    g_wfrag16[idx] = o;
}

// ---------------------------------------------------------------------------
// Precompute via fp16 warp-mma (m16n8k16), fp32 accumulate.
// One warp = 32 rows x 128 cols. Block = 128 threads (4 warps), 128 rows.
// smem: 4 warps x 32 rows x 136 halves = 34.8 KB (static cap OK).
// Row stride 272 B: conflict-free for ldmatrix (8 rows -> banks 4r+c),
// staging STS.64, and epilogue half2 STS. Fully warp-synchronous.
// Per k-chunk (k=16): 8 LDG.128 (B), 2 ldmatrix.x4 (A), 32 mma.
// ---------------------------------------------------------------------------
__global__ __launch_bounds__(128) void precompute_mma(
    const float* __restrict__ z_user, const float* __restrict__ z_item,
    const float* __restrict__ b1,
    int n_user, int n_item, int nb_user)
{
    __shared__ __half sA[4][32][136];

    const int warp = threadIdx.x >> 5;
    const int lane = threadIdx.x & 31;

    const bool is_user = (int)blockIdx.x < nb_user;
    const float* Z;
    __half* P;
    int nrows, tb, blk;
    if (is_user) { Z = z_user; P = g_p_user; nrows = n_user; tb = 0; blk = blockIdx.x; }
    else         { Z = z_item; P = g_p_item; nrows = n_item; tb = 1; blk = blockIdx.x - nb_user; }

    const int row0 = blk * 128 + warp * 32;
    if (row0 >= nrows) return;   // warp-uniform, no block barriers anywhere

    __half (*sa)[136] = sA[warp];

    // Stage 32 rows as fp16: 1 LDG.128 + cvt + 1 STS.64 per row.
#pragma unroll 8
    for (int r = 0; r < 32; r++) {
        int rr = row0 + r;
        if (rr >= nrows) rr = nrows - 1;
        float4 v = __ldg(reinterpret_cast<const float4*>(Z + (size_t)rr * H) + lane);
        __half2 h0 = __floats2half2_rn(v.x, v.y);
        __half2 h1 = __floats2half2_rn(v.z, v.w);
        uint2 pk = { *reinterpret_cast<uint32_t*>(&h0), *reinterpret_cast<uint32_t*>(&h1) };
        *reinterpret_cast<uint2*>(&sa[r][lane * 4]) = pk;
    }
    __syncwarp();

    float acc[2][16][4];
#pragma unroll
    for (int rt = 0; rt < 2; rt++)
#pragma unroll
        for (int t = 0; t < 16; t++)
#pragma unroll
            for (int c = 0; c < 4; c++) acc[rt][t][c] = 0.f;

    // ldmatrix address: matrix q (lane/8), row-in-matrix (lane%8)
    const int q  = lane >> 3;
    const int rq = lane & 7;
    const int lrow = ((q & 1) ? 8 : 0) + rq;   // +8 rows for a1/a3
    const int lcol = (q >> 1) ? 8 : 0;         // +8 k for a2/a3

    const uint4* wf = g_wfrag16 + (size_t)tb * 8 * 8 * 32 + lane;

#pragma unroll
    for (int kc = 0; kc < 8; kc++) {
        // B fragments: 8 uint4 (16 coltiles), batched for MLP
        uint4 b[8];
        const uint4* wfs = wf + (size_t)kc * 8 * 32;
#pragma unroll
        for (int tp = 0; tp < 8; tp++) b[tp] = __ldg(wfs + (size_t)tp * 32);

        // A fragments for both 16-row tiles
        uint32_t a[2][4];
#pragma unroll
        for (int rt = 0; rt < 2; rt++) {
            uint32_t addr = smem_u32(&sa[rt * 16 + lrow][kc * 16 + lcol]);
            asm volatile(
                "ldmatrix.sync.aligned.m8n8.x4.shared.b16 {%0,%1,%2,%3}, [%4];"
                : "=r"(a[rt][0]), "=r"(a[rt][1]), "=r"(a[rt][2]), "=r"(a[rt][3])
                : "r"(addr));
        }

#pragma unroll
        for (int tp = 0; tp < 8; tp++) {
#pragma unroll
            for (int rt = 0; rt < 2; rt++) {
                MMA_F16(acc[rt][2 * tp],     a[rt][0], a[rt][1], a[rt][2], a[rt][3],
                        b[tp].x, b[tp].y);
                MMA_F16(acc[rt][2 * tp + 1], a[rt][0], a[rt][1], a[rt][2], a[rt][3],
                        b[tp].z, b[tp].w);
            }
        }
    }

    // Epilogue: bias (user only, fp32) -> fp16 -> warp-private smem
    // (conflict-free half2 STS) -> coalesced LDS.128 + STG.128.
    __syncwarp();
    char* se = reinterpret_cast<char*>(sa);   // row r at byte r*272
    const int qr = lane >> 2;
    const int qc = lane & 3;

#pragma unroll
    for (int t = 0; t < 16; t++) {
        float bx = 0.f, by = 0.f;
        if (is_user) {
            float2 bb = *reinterpret_cast<const float2*>(b1 + 8 * t + 2 * qc);
            bx = bb.x; by = bb.y;
        }
        int cb = (8 * t + 2 * qc) * 2;   // byte offset of half2 within row
#pragma unroll
        for (int rt = 0; rt < 2; rt++) {
            __half2 hlo = __floats2half2_rn(acc[rt][t][0] + bx, acc[rt][t][1] + by);
            __half2 hhi = __floats2half2_rn(acc[rt][t][2] + bx, acc[rt][t][3] + by);
            int rlo = rt * 16 + qr;
            *reinterpret_cast<__half2*>(se + (size_t)rlo * 272 + cb) = hlo;
            *reinterpret_cast<__half2*>(se + (size_t)(rlo + 8) * 272 + cb) = hhi;
        }
    }
    __syncwarp();

    // Write out: 2 rows per instruction, 512 B coalesced.
    const int rl = lane >> 4;
    const int cl = lane & 15;
#pragma unroll
    for (int i = 0; i < 16; i++) {
        int r  = 2 * i + rl;
        int gr = row0 + r;
        uint4 v = *reinterpret_cast<uint4*>(se + (size_t)r * 272 + cl * 16);
        if (gr < nrows)
            *reinterpret_cast<uint4*>(P + (size_t)gr * H + cl * 8) = v;
    }
}

// ---------------------------------------------------------------------------
// Edge kernel: 8 lanes per edge, 8 edges per warp-iteration. Grid-stride.
//   out[e] = sum_c relu(pu[row[e]][c] + pi[col[e]][c]) * W2[c] + b2
// ---------------------------------------------------------------------------
__global__ __launch_bounds__(256) void edge_kernel(
    const int* __restrict__ row, const int* __restrict__ col,
    const float* __restrict__ W2, const float* __restrict__ b2,
    float* __restrict__ out, int E)
{
    const int lane = threadIdx.x & 31;
    const int sub  = lane >> 3;
    const int l    = lane & 7;

    float w2v[16];
#pragma unroll
    for (int i = 0; i < 16; i++) w2v[i] = __ldg(W2 + l * 16 + i);
    const float b2v = __ldg(b2);

    const int warp_global = (int)((blockIdx.x * 256u + threadIdx.x) >> 5);
    const int total_warps = (int)((gridDim.x * 256u) >> 5);

    for (int eb = warp_global * 8; eb < E; eb += total_warps * 8) {
        int e0 = eb + sub;
        int e1 = eb + sub + 4;
        int e0c = (e0 < E) ? e0 : (E - 1);
        int e1c = (e1 < E) ? e1 : (E - 1);

        const int u0 = __ldg(row + e0c);
        const int v0 = __ldg(col + e0c);
        const int u1 = __ldg(row + e1c);
        const int v1 = __ldg(col + e1c);

        const uint4* pu0 = reinterpret_cast<const uint4*>(g_p_user + (size_t)u0 * H) + l * 2;
        const uint4* pi0 = reinterpret_cast<const uint4*>(g_p_item + (size_t)v0 * H) + l * 2;
        const uint4* pu1 = reinterpret_cast<const uint4*>(g_p_user + (size_t)u1 * H) + l * 2;
        const uint4* pi1 = reinterpret_cast<const uint4*>(g_p_item + (size_t)v1 * H) + l * 2;

        uint4 A0 = pu0[0], A1 = pu0[1];
        uint4 C0 = pi0[0], C1 = pi0[1];
        uint4 B0 = pu1[0], B1 = pu1[1];
        uint4 D0 = pi1[0], D1 = pi1[1];

        float s0 = 0.f, s1 = 0.f;
        const __half2* a0 = reinterpret_cast<const __half2*>(&A0);
        const __half2* a1 = reinterpret_cast<const __half2*>(&A1);
        const __half2* c0 = reinterpret_cast<const __half2*>(&C0);
        const __half2* c1 = reinterpret_cast<const __half2*>(&C1);
        const __half2* bb0 = reinterpret_cast<const __half2*>(&B0);
        const __half2* bb1 = reinterpret_cast<const __half2*>(&B1);
        const __half2* d0 = reinterpret_cast<const __half2*>(&D0);
        const __half2* d1 = reinterpret_cast<const __half2*>(&D1);

#pragma unroll
        for (int j = 0; j < 4; j++) {
            float2 fa = __half22float2(a0[j]);
            float2 fb = __half22float2(c0[j]);
            s0 = fmaf(fmaxf(fa.x + fb.x, 0.f), w2v[2 * j],     s0);
            s0 = fmaf(fmaxf(fa.y + fb.y, 0.f), w2v[2 * j + 1], s0);
            float2 ga = __half22float2(bb0[j]);
            float2 gb = __half22float2(d0[j]);
            s1 = fmaf(fmaxf(ga.x + gb.x, 0.f), w2v[2 * j],     s1);
            s1 = fmaf(fmaxf(ga.y + gb.y, 0.f), w2v[2 * j + 1], s1);
        }
#pragma unroll
        for (int j = 0; j < 4; j++) {
            float2 fa = __half22float2(a1[j]);
            float2 fb = __half22float2(c1[j]);
            s0 = fmaf(fmaxf(fa.x + fb.x, 0.f), w2v[8 + 2 * j],     s0);
            s0 = fmaf(fmaxf(fa.y + fb.y, 0.f), w2v[8 + 2 * j + 1], s0);
            float2 ga = __half22float2(bb1[j]);
            float2 gb = __half22float2(d1[j]);
            s1 = fmaf(fmaxf(ga.x + gb.x, 0.f), w2v[8 + 2 * j],     s1);
            s1 = fmaf(fmaxf(ga.y + gb.y, 0.f), w2v[8 + 2 * j + 1], s1);
        }

#pragma unroll
        for (int off = 4; off; off >>= 1) {
            s0 += __shfl_xor_sync(0xFFFFFFFFu, s0, off);
            s1 += __shfl_xor_sync(0xFFFFFFFFu, s1, off);
        }

        if (l == 0) {
            if (e0 < E) out[e0] = s0 + b2v;
            if (e1 < E) out[e1] = s1 + b2v;
        }
    }
}

// ---------------------------------------------------------------------------
// Inputs (metadata order): z_user f32[100000*128], z_item f32[50000*128],
//   row i32[E], col i32[E], W1 f32[256*128], b1 f32[128], W2 f32[128], b2 f32[1]
// Output: f32[E]
// ---------------------------------------------------------------------------
extern "C" void kernel_launch(void* const* d_in, const int* in_sizes, int n_in,
                              void* d_out, int out_size)
{
    const float* z_user = (const float*)d_in[0];
    const float* z_item = (const float*)d_in[1];
    const int*   row    = (const int*)d_in[2];
    const int*   col    = (const int*)d_in[3];
    const float* W1     = (const float*)d_in[4];
    const float* b1     = (const float*)d_in[5];
    const float* W2     = (const float*)d_in[6];
    const float* b2     = (const float*)d_in[7];
    float* out = (float*)d_out;

    const int n_user = in_sizes[0] / H;
    const int n_item = in_sizes[1] / H;
    const int E      = in_sizes[2];

    const int nb_user = (n_user + 127) / 128;
    const int nb_item = (n_item + 127) / 128;

    convert_w<<<16, 256>>>(W1);
    precompute_mma<<<nb_user + nb_item, 128>>>(z_user, z_item, b1,
                                               n_user, n_item, nb_user);
    edge_kernel<<<1184, 256>>>(row, col, W2, b2, out, E);
}